// round 13
// baseline (speedup 1.0000x reference)
#include <cuda_runtime.h>
#include <cuda_fp16.h>
#include <math.h>
#include <stdint.h>

#define B_DIM 1024
#define D_DIM 512
#define C_DIM 51332
#define C_TILES 402
#define C_PAD (C_TILES * 128)       // 51456

#define EPS_F   1e-3f
#define SCALE_F 64.0f

// ---------------- persistent device scratch (no runtime allocation) --------
__device__ __align__(256) float  g_invnorm[C_PAD];
__device__ __align__(256) __half g_kf16[(size_t)D_DIM * C_PAD];  // kernel fp16 [D, C_PAD]
__device__ __align__(256) __half g_ef16[B_DIM * D_DIM];          // emb fp16 [B, D]

// ---------------------------------------------------------------------------
// Kernel 1: fused fp16-convert + column sumsq + invnorm, 4 columns per thread
// ---------------------------------------------------------------------------
__global__ void kprep_kernel(const float* __restrict__ kern) {
    int c0 = (blockIdx.x * blockDim.x + threadIdx.x) * 4;
    if (c0 >= C_PAD) return;
    if (c0 >= C_DIM) {   // pure padding: zero-fill
        uint2 z = make_uint2(0u, 0u);
        for (int d = 0; d < D_DIM; ++d)
            *reinterpret_cast<uint2*>(g_kf16 + (size_t)d * C_PAD + c0) = z;
        return;
    }
    float s0 = 0.f, s1 = 0.f, s2 = 0.f, s3 = 0.f;
#pragma unroll 4
    for (int d = 0; d < D_DIM; ++d) {
        float4 v = *reinterpret_cast<const float4*>(kern + (size_t)d * C_DIM + c0);
        s0 = fmaf(v.x, v.x, s0);
        s1 = fmaf(v.y, v.y, s1);
        s2 = fmaf(v.z, v.z, s2);
        s3 = fmaf(v.w, v.w, s3);
        __half2 h01 = __floats2half2_rn(v.x, v.y);
        __half2 h23 = __floats2half2_rn(v.z, v.w);
        uint2 u;
        u.x = *reinterpret_cast<uint32_t*>(&h01);
        u.y = *reinterpret_cast<uint32_t*>(&h23);
        *reinterpret_cast<uint2*>(g_kf16 + (size_t)d * C_PAD + c0) = u;
    }
    float4 inv;
    inv.x = 1.0f / fmaxf(sqrtf(s0), 1e-5f);
    inv.y = 1.0f / fmaxf(sqrtf(s1), 1e-5f);
    inv.z = 1.0f / fmaxf(sqrtf(s2), 1e-5f);
    inv.w = 1.0f / fmaxf(sqrtf(s3), 1e-5f);
    *reinterpret_cast<float4*>(g_invnorm + c0) = inv;
}

// ---------------------------------------------------------------------------
// Kernel 2: embeddings -> fp16
// ---------------------------------------------------------------------------
__global__ void ef16_kernel(const float* __restrict__ emb) {
    int i = (blockIdx.x * blockDim.x + threadIdx.x) * 4;
    if (i >= B_DIM * D_DIM) return;
    float4 v = *reinterpret_cast<const float4*>(emb + i);
    __half2 h01 = __floats2half2_rn(v.x, v.y);
    __half2 h23 = __floats2half2_rn(v.z, v.w);
    uint2 u;
    u.x = *reinterpret_cast<uint32_t*>(&h01);
    u.y = *reinterpret_cast<uint32_t*>(&h23);
    *reinterpret_cast<uint2*>(g_ef16 + i) = u;
}

// ---------------------------------------------------------------------------
// Kernel 3: fp16 mma.sync GEMM, 128x128 tile, BKK=32, 3-stage cp.async,
// ONE __syncthreads per stage (safe with 3 buffers; loader byte-exact R10)
// ---------------------------------------------------------------------------
#define BKK 32
#define AS_STRIDE 40
#define BS_STRIDE 136
#define A_TILE (128 * AS_STRIDE)
#define B_TILE (BKK * BS_STRIDE)
#define STAGES 3
#define NSTAGE 16
#define SMEM_BYTES (STAGES * (A_TILE + B_TILE) * 2)

__device__ __forceinline__ unsigned sptr(const void* p) {
    return (unsigned)__cvta_generic_to_shared(p);
}
__device__ __forceinline__ void cp16(unsigned dst, const void* src) {
    asm volatile("cp.async.cg.shared.global [%0], [%1], 16;" :: "r"(dst), "l"(src));
}
__device__ __forceinline__ void ldsm_x4(uint32_t* r, unsigned addr) {
    asm volatile("ldmatrix.sync.aligned.m8n8.x4.shared.b16 {%0,%1,%2,%3}, [%4];"
                 : "=r"(r[0]), "=r"(r[1]), "=r"(r[2]), "=r"(r[3]) : "r"(addr));
}
__device__ __forceinline__ void ldsm_x2t(uint32_t* r, unsigned addr) {
    asm volatile("ldmatrix.sync.aligned.m8n8.x2.trans.shared.b16 {%0,%1}, [%2];"
                 : "=r"(r[0]), "=r"(r[1]) : "r"(addr));
}
__device__ __forceinline__ void mma16816(float* c, const uint32_t* a, const uint32_t* b) {
    asm volatile("mma.sync.aligned.m16n8k16.row.col.f32.f16.f16.f32 "
                 "{%0,%1,%2,%3}, {%4,%5,%6,%7}, {%8,%9}, {%0,%1,%2,%3};"
                 : "+f"(c[0]), "+f"(c[1]), "+f"(c[2]), "+f"(c[3])
                 : "r"(a[0]), "r"(a[1]), "r"(a[2]), "r"(a[3]), "r"(b[0]), "r"(b[1]));
}

__global__ __launch_bounds__(256, 2)
void gemm_f16_kernel(float* __restrict__ out)
{
    extern __shared__ __half smem[];
    __half* sA = smem;                       // STAGES * A_TILE
    __half* sB = smem + STAGES * A_TILE;     // STAGES * B_TILE

    const int tid  = threadIdx.x;
    const int lane = tid & 31;
    const int warp = tid >> 5;
    const int wm   = warp >> 2;      // 0..1
    const int wn   = warp & 3;       // 0..3
    const int rowBase = blockIdx.x * 128;
    const int colBase = blockIdx.y * 128;

    float acc[4][4][4];
#pragma unroll
    for (int i = 0; i < 4; ++i)
#pragma unroll
        for (int j = 0; j < 4; ++j)
#pragma unroll
            for (int q = 0; q < 4; ++q) acc[i][j][q] = 0.0f;

    // byte-exact R10 loader (cp16 = 16 bytes = 8 halves; offsets in halves: ch*8)
    auto load_stage = [&](int ks, int buf) {
        const int k0 = ks * BKK;
#pragma unroll
        for (int r = 0; r < 2; ++r) {
            int t   = tid + r * 256;
            int row = t >> 2;
            int ch  = t & 3;
            cp16(sptr(sA + buf * A_TILE + row * AS_STRIDE + ch * 8),
                 g_ef16 + (size_t)(rowBase + row) * D_DIM + k0 + ch * 8);
        }
#pragma unroll
        for (int r = 0; r < 2; ++r) {
            int t   = tid + r * 256;
            int row = t >> 4;
            int ch  = t & 15;
            cp16(sptr(sB + buf * B_TILE + row * BS_STRIDE + ch * 8),
                 g_kf16 + (size_t)(k0 + row) * C_PAD + colBase + ch * 8);
        }
        asm volatile("cp.async.commit_group;");
    };

    auto compute_stage = [&](int buf) {
        const __half* A  = sA + buf * A_TILE;
        const __half* Bt = sB + buf * B_TILE;
#pragma unroll
        for (int h = 0; h < 2; ++h) {
            const int k16 = h * 16;
            uint32_t af[4][4], bf[4][2];
#pragma unroll
            for (int mt = 0; mt < 4; ++mt) {
                int row = wm * 64 + mt * 16 + (lane & 15);
                int kc  = k16 + (lane >> 4) * 8;
                ldsm_x4(af[mt], sptr(A + row * AS_STRIDE + kc));
            }
#pragma unroll
            for (int nt = 0; nt < 4; ++nt) {
                int krow = k16 + (lane & 15);
                int nc   = wn * 32 + nt * 8;
                ldsm_x2t(bf[nt], sptr(Bt + krow * BS_STRIDE + nc));
            }
#pragma unroll
            for (int mt = 0; mt < 4; ++mt)
#pragma unroll
                for (int nt = 0; nt < 4; ++nt)
                    mma16816(acc[mt][nt], af[mt], bf[nt]);
        }
    };

    // ---- 3-stage pipeline, one sync per stage ----
    load_stage(0, 0);
    load_stage(1, 1);
    for (int i = 0; i < NSTAGE; ++i) {
        if (i < NSTAGE - 1) asm volatile("cp.async.wait_group 1;");
        else                asm volatile("cp.async.wait_group 0;");
        __syncthreads();
        // all threads finished compute(i-1) before this sync -> buffer (i+2)%3 free
        if (i + 2 < NSTAGE) load_stage(i + 2, (i + 2) % STAGES);
        compute_stage(i % STAGES);
    }

    // epilogue: * invnorm[c], clip, * scale
#pragma unroll
    for (int mt = 0; mt < 4; ++mt) {
#pragma unroll
        for (int nt = 0; nt < 4; ++nt) {
            int col = colBase + wn * 32 + nt * 8 + (lane & 3) * 2;
            if (col >= C_DIM) continue;
            float2 inv = *reinterpret_cast<const float2*>(g_invnorm + col);
#pragma unroll
            for (int rr = 0; rr < 2; ++rr) {
                int row = rowBase + wm * 64 + mt * 16 + (lane >> 2) + rr * 8;
                float2 v;
                v.x = fminf(fmaxf(acc[mt][nt][rr * 2 + 0] * inv.x, -1.0f + EPS_F), 1.0f - EPS_F) * SCALE_F;
                v.y = fminf(fmaxf(acc[mt][nt][rr * 2 + 1] * inv.y, -1.0f + EPS_F), 1.0f - EPS_F) * SCALE_F;
                *reinterpret_cast<float2*>(out + (size_t)row * C_DIM + col) = v;
            }
        }
    }
}

// ---------------------------------------------------------------------------
// Kernel 4: patch label entries with the AdaFace margin (exact fp32)
// ---------------------------------------------------------------------------
__global__ void patch_label_kernel(const float* __restrict__ emb,
                                   const float* __restrict__ norms,
                                   const float* __restrict__ kern,
                                   const int*   __restrict__ label,
                                   float* __restrict__ out)
{
    int warp = (blockIdx.x * blockDim.x + threadIdx.x) >> 5;
    int lane = threadIdx.x & 31;
    if (warp >= B_DIM) return;

    int col = label[warp];
    const float* erow = emb + (size_t)warp * D_DIM;

    float sum = 0.0f;
#pragma unroll
    for (int d = lane; d < D_DIM; d += 32)
        sum = fmaf(erow[d], kern[(size_t)d * C_DIM + col], sum);
#pragma unroll
    for (int o = 16; o; o >>= 1)
        sum += __shfl_xor_sync(0xffffffffu, sum, o);

    if (lane == 0) {
        float cosv = sum * g_invnorm[col];
        cosv = fminf(fmaxf(cosv, -1.0f + EPS_F), 1.0f - EPS_F);

        float sn = fminf(fmaxf(norms[warp], 1e-3f), 100.0f);
        float ms = sn / (100.0f + EPS_F) * 0.333f;        // BATCH_MEAN = 0
        ms = fminf(fmaxf(ms, -1.0f), 1.0f);

        float theta = acosf(cosv) + 0.5f * ms;            // M = 0.5
        const float PI_F = 3.14159265358979323846f;
        theta = fminf(fmaxf(theta, EPS_F), PI_F - EPS_F);
        float cm = cosf(theta) - (0.5f - 0.5f * ms);      // HEAD_B = 0.5
        out[(size_t)warp * C_DIM + col] = cm * SCALE_F;
    }
}

// ---------------------------------------------------------------------------
extern "C" void kernel_launch(void* const* d_in, const int* in_sizes, int n_in,
                              void* d_out, int out_size)
{
    const float* emb   = (const float*)d_in[0];  // [1024, 512]
    const float* norms = (const float*)d_in[1];  // [1024, 1]
    const float* kern  = (const float*)d_in[2];  // [512, 51332]
    const int*   label = (const int*)  d_in[3];  // [1024]
    float*       out   = (float*)d_out;          // [1024, 51332]

    cudaFuncSetAttribute(gemm_f16_kernel,
                         cudaFuncAttributeMaxDynamicSharedMemorySize, SMEM_BYTES);

    kprep_kernel<<<(C_PAD / 4 + 255) / 256, 256>>>(kern);
    ef16_kernel<<<(B_DIM * D_DIM / 4 + 255) / 256, 256>>>(emb);

    dim3 ggrid(B_DIM / 128, C_TILES);   // row tile fastest -> B slab L2 reuse
    gemm_f16_kernel<<<ggrid, 256, SMEM_BYTES>>>(out);

    patch_label_kernel<<<(B_DIM * 32) / 256, 256>>>(emb, norms, kern, label, out);
}

// round 14
// speedup vs baseline: 1.2762x; 1.2762x over previous
#include <cuda_runtime.h>
#include <cuda_fp16.h>
#include <math.h>
#include <stdint.h>

#define B_DIM 1024
#define D_DIM 512
#define C_DIM 51332
#define C_TILES 402
#define C_PAD (C_TILES * 128)       // 51456

#define EPS_F   1e-3f
#define SCALE_F 64.0f

// ---------------- persistent device scratch (no runtime allocation) --------
__device__ __align__(256) float  g_part[4 * C_PAD];              // partial col sumsq
__device__ __align__(256) float  g_invnorm[C_PAD];
__device__ __align__(256) __half g_kf16[(size_t)D_DIM * C_PAD];  // kernel fp16 [D, C_PAD]
__device__ __align__(256) __half g_ef16[B_DIM * D_DIM];          // emb fp16 [B, D]

// ---------------------------------------------------------------------------
// Kernel 1: fp16-convert + partial column sumsq, split 4x along d for occupancy
// grid (C_PAD/128, 4): block by handles d in [by*128, by*128+128)
// ---------------------------------------------------------------------------
__global__ void kprep_part_kernel(const float* __restrict__ kern) {
    int c = blockIdx.x * blockDim.x + threadIdx.x;   // blockDim = 128
    if (c >= C_PAD) return;
    const int d0 = blockIdx.y * 128;
    if (c >= C_DIM) {   // padding columns: zero-fill fp16, zero partial
        for (int d = d0; d < d0 + 128; ++d)
            g_kf16[(size_t)d * C_PAD + c] = __ushort_as_half((unsigned short)0);
        g_part[blockIdx.y * C_PAD + c] = 0.0f;
        return;
    }
    float s0 = 0.f, s1 = 0.f, s2 = 0.f, s3 = 0.f;
#pragma unroll 8
    for (int d = d0; d < d0 + 128; d += 4) {
        float v0 = kern[(size_t)(d + 0) * C_DIM + c];
        float v1 = kern[(size_t)(d + 1) * C_DIM + c];
        float v2 = kern[(size_t)(d + 2) * C_DIM + c];
        float v3 = kern[(size_t)(d + 3) * C_DIM + c];
        s0 = fmaf(v0, v0, s0);
        s1 = fmaf(v1, v1, s1);
        s2 = fmaf(v2, v2, s2);
        s3 = fmaf(v3, v3, s3);
        g_kf16[(size_t)(d + 0) * C_PAD + c] = __float2half_rn(v0);
        g_kf16[(size_t)(d + 1) * C_PAD + c] = __float2half_rn(v1);
        g_kf16[(size_t)(d + 2) * C_PAD + c] = __float2half_rn(v2);
        g_kf16[(size_t)(d + 3) * C_PAD + c] = __float2half_rn(v3);
    }
    g_part[blockIdx.y * C_PAD + c] = (s0 + s1) + (s2 + s3);
}

// ---------------------------------------------------------------------------
// Kernel 2: reduce partials -> invnorm (deterministic order)
// ---------------------------------------------------------------------------
__global__ void invnorm_kernel() {
    int c = blockIdx.x * blockDim.x + threadIdx.x;
    if (c >= C_DIM) return;
    float s = ((g_part[c] + g_part[C_PAD + c]) +
               (g_part[2 * C_PAD + c] + g_part[3 * C_PAD + c]));
    g_invnorm[c] = 1.0f / fmaxf(sqrtf(s), 1e-5f);
}

// ---------------------------------------------------------------------------
// Kernel 3: embeddings -> fp16
// ---------------------------------------------------------------------------
__global__ void ef16_kernel(const float* __restrict__ emb) {
    int i = (blockIdx.x * blockDim.x + threadIdx.x) * 4;
    if (i >= B_DIM * D_DIM) return;
    float4 v = *reinterpret_cast<const float4*>(emb + i);
    __half2 h01 = __floats2half2_rn(v.x, v.y);
    __half2 h23 = __floats2half2_rn(v.z, v.w);
    uint2 u;
    u.x = *reinterpret_cast<uint32_t*>(&h01);
    u.y = *reinterpret_cast<uint32_t*>(&h23);
    *reinterpret_cast<uint2*>(g_ef16 + i) = u;
}

// ---------------------------------------------------------------------------
// Kernel 4: fp16 mma.sync GEMM — byte-exact R10 (proven 250.4us) config
// Tile 128x128x32, 256 threads, warps 2x4, 2-stage cp.async, static smem
// ---------------------------------------------------------------------------
#define BKK 32
#define AS_STRIDE 40
#define BS_STRIDE 136
#define A_TILE (128 * AS_STRIDE)
#define B_TILE (BKK * BS_STRIDE)

__device__ __forceinline__ unsigned sptr(const void* p) {
    return (unsigned)__cvta_generic_to_shared(p);
}
__device__ __forceinline__ void cp16(unsigned dst, const void* src) {
    asm volatile("cp.async.cg.shared.global [%0], [%1], 16;" :: "r"(dst), "l"(src));
}
__device__ __forceinline__ void ldsm_x4(uint32_t* r, unsigned addr) {
    asm volatile("ldmatrix.sync.aligned.m8n8.x4.shared.b16 {%0,%1,%2,%3}, [%4];"
                 : "=r"(r[0]), "=r"(r[1]), "=r"(r[2]), "=r"(r[3]) : "r"(addr));
}
__device__ __forceinline__ void ldsm_x2t(uint32_t* r, unsigned addr) {
    asm volatile("ldmatrix.sync.aligned.m8n8.x2.trans.shared.b16 {%0,%1}, [%2];"
                 : "=r"(r[0]), "=r"(r[1]) : "r"(addr));
}
__device__ __forceinline__ void mma16816(float* c, const uint32_t* a, const uint32_t* b) {
    asm volatile("mma.sync.aligned.m16n8k16.row.col.f32.f16.f16.f32 "
                 "{%0,%1,%2,%3}, {%4,%5,%6,%7}, {%8,%9}, {%0,%1,%2,%3};"
                 : "+f"(c[0]), "+f"(c[1]), "+f"(c[2]), "+f"(c[3])
                 : "r"(a[0]), "r"(a[1]), "r"(a[2]), "r"(a[3]), "r"(b[0]), "r"(b[1]));
}

__global__ __launch_bounds__(256, 2)
void gemm_f16_kernel(float* __restrict__ out)
{
    __shared__ __half sA[2 * A_TILE];
    __shared__ __half sB[2 * B_TILE];

    const int tid  = threadIdx.x;
    const int lane = tid & 31;
    const int warp = tid >> 5;
    const int wm   = warp >> 2;      // 0..1
    const int wn   = warp & 3;       // 0..3
    const int rowBase = blockIdx.x * 128;   // row tile fastest -> B slab L2 reuse
    const int colBase = blockIdx.y * 128;

    float acc[4][4][4];
#pragma unroll
    for (int i = 0; i < 4; ++i)
#pragma unroll
        for (int j = 0; j < 4; ++j)
#pragma unroll
            for (int q = 0; q < 4; ++q) acc[i][j][q] = 0.0f;

    auto load_stage = [&](int ks, int buf) {
        const int k0 = ks * BKK;
#pragma unroll
        for (int r = 0; r < 2; ++r) {
            int t   = tid + r * 256;
            int row = t >> 2;
            int ch  = t & 3;
            cp16(sptr(sA + buf * A_TILE + row * AS_STRIDE + ch * 8),
                 g_ef16 + (size_t)(rowBase + row) * D_DIM + k0 + ch * 8);
        }
#pragma unroll
        for (int r = 0; r < 2; ++r) {
            int t   = tid + r * 256;
            int row = t >> 4;
            int ch  = t & 15;
            cp16(sptr(sB + buf * B_TILE + row * BS_STRIDE + ch * 8),
                 g_kf16 + (size_t)(k0 + row) * C_PAD + colBase + ch * 8);
        }
    };

    auto compute_stage = [&](int buf) {
        const __half* A  = sA + buf * A_TILE;
        const __half* Bt = sB + buf * B_TILE;
#pragma unroll
        for (int h = 0; h < 2; ++h) {
            const int k16 = h * 16;
            uint32_t af[4][4], bf[4][2];
#pragma unroll
            for (int mt = 0; mt < 4; ++mt) {
                int row = wm * 64 + mt * 16 + (lane & 15);
                int kc  = k16 + (lane >> 4) * 8;
                ldsm_x4(af[mt], sptr(A + row * AS_STRIDE + kc));
            }
#pragma unroll
            for (int nt = 0; nt < 4; ++nt) {
                int krow = k16 + (lane & 15);
                int nc   = wn * 32 + nt * 8;
                ldsm_x2t(bf[nt], sptr(Bt + krow * BS_STRIDE + nc));
            }
#pragma unroll
            for (int mt = 0; mt < 4; ++mt)
#pragma unroll
                for (int nt = 0; nt < 4; ++nt)
                    mma16816(acc[mt][nt], af[mt], bf[nt]);
        }
    };

    // ---- proven 2-stage pipeline: 16 stages of K=32 ----
    load_stage(0, 0);
    asm volatile("cp.async.commit_group;");
    for (int ks = 0; ks < 16; ++ks) {
        if (ks + 1 < 16) {
            load_stage(ks + 1, (ks + 1) & 1);
            asm volatile("cp.async.commit_group;");
            asm volatile("cp.async.wait_group 1;");
        } else {
            asm volatile("cp.async.wait_group 0;");
        }
        __syncthreads();
        compute_stage(ks & 1);
        __syncthreads();
    }

    // epilogue: * invnorm[c], clip, * scale
#pragma unroll
    for (int mt = 0; mt < 4; ++mt) {
#pragma unroll
        for (int nt = 0; nt < 4; ++nt) {
            int col = colBase + wn * 32 + nt * 8 + (lane & 3) * 2;
            if (col >= C_DIM) continue;
            float2 inv = *reinterpret_cast<const float2*>(g_invnorm + col);
#pragma unroll
            for (int rr = 0; rr < 2; ++rr) {
                int row = rowBase + wm * 64 + mt * 16 + (lane >> 2) + rr * 8;
                float2 v;
                v.x = fminf(fmaxf(acc[mt][nt][rr * 2 + 0] * inv.x, -1.0f + EPS_F), 1.0f - EPS_F) * SCALE_F;
                v.y = fminf(fmaxf(acc[mt][nt][rr * 2 + 1] * inv.y, -1.0f + EPS_F), 1.0f - EPS_F) * SCALE_F;
                *reinterpret_cast<float2*>(out + (size_t)row * C_DIM + col) = v;
            }
        }
    }
}

// ---------------------------------------------------------------------------
// Kernel 5: patch label entries IN-PLACE from the GEMM output.
// out[b, label] already holds S*clip(cosine); recover cosine = out/S (it is
// the clipped value, exactly what arccos consumes in the reference).
// One thread per row — no strided kernel-column walk.
// ---------------------------------------------------------------------------
__global__ void patch_label_kernel(const float* __restrict__ norms,
                                   const int*   __restrict__ label,
                                   float* __restrict__ out)
{
    int b = blockIdx.x * blockDim.x + threadIdx.x;
    if (b >= B_DIM) return;

    int col = label[b];
    size_t idx = (size_t)b * C_DIM + col;
    float cosv = out[idx] * (1.0f / SCALE_F);   // already clipped to (-1+eps, 1-eps)

    float sn = fminf(fmaxf(norms[b], 1e-3f), 100.0f);
    float ms = sn / (100.0f + EPS_F) * 0.333f;        // BATCH_MEAN = 0
    ms = fminf(fmaxf(ms, -1.0f), 1.0f);

    float theta = acosf(cosv) + 0.5f * ms;            // M = 0.5
    const float PI_F = 3.14159265358979323846f;
    theta = fminf(fmaxf(theta, EPS_F), PI_F - EPS_F);
    float cm = cosf(theta) - (0.5f - 0.5f * ms);      // HEAD_B = 0.5
    out[idx] = cm * SCALE_F;
}

// ---------------------------------------------------------------------------
extern "C" void kernel_launch(void* const* d_in, const int* in_sizes, int n_in,
                              void* d_out, int out_size)
{
    const float* emb   = (const float*)d_in[0];  // [1024, 512]
    const float* norms = (const float*)d_in[1];  // [1024, 1]
    const float* kern  = (const float*)d_in[2];  // [512, 51332]
    const int*   label = (const int*)  d_in[3];  // [1024]
    float*       out   = (float*)d_out;          // [1024, 51332]

    dim3 pgrid(C_PAD / 128, 4);
    kprep_part_kernel<<<pgrid, 128>>>(kern);
    invnorm_kernel<<<(C_DIM + 255) / 256, 256>>>();

    ef16_kernel<<<(B_DIM * D_DIM / 4 + 255) / 256, 256>>>(emb);

    dim3 ggrid(B_DIM / 128, C_TILES);   // row tile fastest -> B slab L2 reuse
    gemm_f16_kernel<<<ggrid, 256>>>(out);

    patch_label_kernel<<<(B_DIM + 255) / 256, 256>>>(norms, label, out);
}

// round 15
// speedup vs baseline: 1.3614x; 1.0668x over previous
#include <cuda_runtime.h>
#include <cuda_fp16.h>
#include <math.h>
#include <stdint.h>

#define B_DIM 1024
#define D_DIM 512
#define C_DIM 51332
#define C_TILES 402
#define C_PAD (C_TILES * 128)       // 51456

#define EPS_F   1e-3f
#define SCALE_F 64.0f

// ---------------- persistent device scratch (no runtime allocation) --------
__device__ __align__(256) float  g_part[4 * C_PAD];              // partial col sumsq
__device__ __align__(256) float  g_invnorm[C_PAD];
__device__ __align__(256) __half g_kf16[(size_t)D_DIM * C_PAD];  // kernel fp16 [D, C_PAD]
__device__ __align__(256) __half g_ef16[B_DIM * D_DIM];          // emb fp16 [B, D]

// ---------------------------------------------------------------------------
// Kernel 1: fp16-convert + partial column sumsq, split 4x along d for occupancy
// ---------------------------------------------------------------------------
__global__ void kprep_part_kernel(const float* __restrict__ kern) {
    int c = blockIdx.x * blockDim.x + threadIdx.x;   // blockDim = 128
    if (c >= C_PAD) return;
    const int d0 = blockIdx.y * 128;
    if (c >= C_DIM) {   // padding columns: zero-fill fp16, zero partial
        for (int d = d0; d < d0 + 128; ++d)
            g_kf16[(size_t)d * C_PAD + c] = __ushort_as_half((unsigned short)0);
        g_part[blockIdx.y * C_PAD + c] = 0.0f;
        return;
    }
    float s0 = 0.f, s1 = 0.f, s2 = 0.f, s3 = 0.f;
#pragma unroll 8
    for (int d = d0; d < d0 + 128; d += 4) {
        float v0 = kern[(size_t)(d + 0) * C_DIM + c];
        float v1 = kern[(size_t)(d + 1) * C_DIM + c];
        float v2 = kern[(size_t)(d + 2) * C_DIM + c];
        float v3 = kern[(size_t)(d + 3) * C_DIM + c];
        s0 = fmaf(v0, v0, s0);
        s1 = fmaf(v1, v1, s1);
        s2 = fmaf(v2, v2, s2);
        s3 = fmaf(v3, v3, s3);
        g_kf16[(size_t)(d + 0) * C_PAD + c] = __float2half_rn(v0);
        g_kf16[(size_t)(d + 1) * C_PAD + c] = __float2half_rn(v1);
        g_kf16[(size_t)(d + 2) * C_PAD + c] = __float2half_rn(v2);
        g_kf16[(size_t)(d + 3) * C_PAD + c] = __float2half_rn(v3);
    }
    g_part[blockIdx.y * C_PAD + c] = (s0 + s1) + (s2 + s3);
}

// ---------------------------------------------------------------------------
// Kernel 2: reduce partials -> invnorm (deterministic order)
// ---------------------------------------------------------------------------
__global__ void invnorm_kernel() {
    int c = blockIdx.x * blockDim.x + threadIdx.x;
    if (c >= C_DIM) return;
    float s = ((g_part[c] + g_part[C_PAD + c]) +
               (g_part[2 * C_PAD + c] + g_part[3 * C_PAD + c]));
    g_invnorm[c] = 1.0f / fmaxf(sqrtf(s), 1e-5f);
}

// ---------------------------------------------------------------------------
// Kernel 3: embeddings -> fp16
// ---------------------------------------------------------------------------
__global__ void ef16_kernel(const float* __restrict__ emb) {
    int i = (blockIdx.x * blockDim.x + threadIdx.x) * 4;
    if (i >= B_DIM * D_DIM) return;
    float4 v = *reinterpret_cast<const float4*>(emb + i);
    __half2 h01 = __floats2half2_rn(v.x, v.y);
    __half2 h23 = __floats2half2_rn(v.z, v.w);
    uint2 u;
    u.x = *reinterpret_cast<uint32_t*>(&h01);
    u.y = *reinterpret_cast<uint32_t*>(&h23);
    *reinterpret_cast<uint2*>(g_ef16 + i) = u;
}

// ---------------------------------------------------------------------------
// Kernel 4: fp16 mma.sync GEMM, 128x128 tile, 128 threads = 4 warps of 64x64.
// 33% less LDSM traffic per MMA vs 64x32 warp tiles; same proven 2-stage
// cp.async pipeline; 2 CTAs/SM preserved (regs ~190, smem 38KB).
// ---------------------------------------------------------------------------
#define BKK 32
#define AS_STRIDE 40
#define BS_STRIDE 136
#define A_TILE (128 * AS_STRIDE)
#define B_TILE (BKK * BS_STRIDE)

__device__ __forceinline__ unsigned sptr(const void* p) {
    return (unsigned)__cvta_generic_to_shared(p);
}
__device__ __forceinline__ void cp16(unsigned dst, const void* src) {
    asm volatile("cp.async.cg.shared.global [%0], [%1], 16;" :: "r"(dst), "l"(src));
}
__device__ __forceinline__ void ldsm_x4(uint32_t* r, unsigned addr) {
    asm volatile("ldmatrix.sync.aligned.m8n8.x4.shared.b16 {%0,%1,%2,%3}, [%4];"
                 : "=r"(r[0]), "=r"(r[1]), "=r"(r[2]), "=r"(r[3]) : "r"(addr));
}
__device__ __forceinline__ void ldsm_x4t(uint32_t* r, unsigned addr) {
    asm volatile("ldmatrix.sync.aligned.m8n8.x4.trans.shared.b16 {%0,%1,%2,%3}, [%4];"
                 : "=r"(r[0]), "=r"(r[1]), "=r"(r[2]), "=r"(r[3]) : "r"(addr));
}
__device__ __forceinline__ void mma16816(float* c, const uint32_t* a, const uint32_t* b) {
    asm volatile("mma.sync.aligned.m16n8k16.row.col.f32.f16.f16.f32 "
                 "{%0,%1,%2,%3}, {%4,%5,%6,%7}, {%8,%9}, {%0,%1,%2,%3};"
                 : "+f"(c[0]), "+f"(c[1]), "+f"(c[2]), "+f"(c[3])
                 : "r"(a[0]), "r"(a[1]), "r"(a[2]), "r"(a[3]), "r"(b[0]), "r"(b[1]));
}

__global__ __launch_bounds__(128, 2)
void gemm_f16_kernel(float* __restrict__ out)
{
    __shared__ __half sA[2 * A_TILE];
    __shared__ __half sB[2 * B_TILE];

    const int tid  = threadIdx.x;
    const int lane = tid & 31;
    const int warp = tid >> 5;       // 0..3
    const int wm   = warp >> 1;      // 0..1 (64-row slab)
    const int wn   = warp & 1;       // 0..1 (64-col slab)
    const int rowBase = blockIdx.x * 128;   // row tile fastest -> B slab L2 reuse
    const int colBase = blockIdx.y * 128;

    float acc[4][8][4];
#pragma unroll
    for (int i = 0; i < 4; ++i)
#pragma unroll
        for (int j = 0; j < 8; ++j)
#pragma unroll
            for (int q = 0; q < 4; ++q) acc[i][j][q] = 0.0f;

    auto load_stage = [&](int ks, int buf) {
        const int k0 = ks * BKK;
        // A: 128 rows x 32 half = 512 x 16B chunks, 4 per thread
#pragma unroll
        for (int r = 0; r < 4; ++r) {
            int t   = tid + r * 128;
            int row = t >> 2;
            int ch  = t & 3;
            cp16(sptr(sA + buf * A_TILE + row * AS_STRIDE + ch * 8),
                 g_ef16 + (size_t)(rowBase + row) * D_DIM + k0 + ch * 8);
        }
        // B: 32 rows x 128 half = 512 x 16B chunks, 4 per thread
#pragma unroll
        for (int r = 0; r < 4; ++r) {
            int t   = tid + r * 128;
            int row = t >> 4;
            int ch  = t & 15;
            cp16(sptr(sB + buf * B_TILE + row * BS_STRIDE + ch * 8),
                 g_kf16 + (size_t)(k0 + row) * C_PAD + colBase + ch * 8);
        }
    };

    auto compute_stage = [&](int buf) {
        const __half* A  = sA + buf * A_TILE;
        const __half* Bt = sB + buf * B_TILE;
#pragma unroll
        for (int h = 0; h < 2; ++h) {
            const int k16 = h * 16;
            uint32_t af[4][4], bf[8][2];
            // A: 4 m-frags of 16 rows (64 rows total per warp)
#pragma unroll
            for (int mt = 0; mt < 4; ++mt) {
                int row = wm * 64 + mt * 16 + (lane & 15);
                int kc  = k16 + (lane >> 4) * 8;
                ldsm_x4(af[mt], sptr(A + row * AS_STRIDE + kc));
            }
            // B: 4 ldsm.x4.trans, each covers k16 x 16 cols (2 n-frags)
            {
                int r = lane & 7;
                int g = lane >> 3;
                int krow = k16 + ((g & 1) << 3) + r;
                int cofs = (g >> 1) << 3;
#pragma unroll
                for (int nt2 = 0; nt2 < 4; ++nt2) {
                    int nc = wn * 64 + nt2 * 16 + cofs;
                    uint32_t rr4[4];
                    ldsm_x4t(rr4, sptr(Bt + krow * BS_STRIDE + nc));
                    bf[nt2 * 2 + 0][0] = rr4[0];
                    bf[nt2 * 2 + 0][1] = rr4[1];
                    bf[nt2 * 2 + 1][0] = rr4[2];
                    bf[nt2 * 2 + 1][1] = rr4[3];
                }
            }
#pragma unroll
            for (int mt = 0; mt < 4; ++mt)
#pragma unroll
                for (int nt = 0; nt < 8; ++nt)
                    mma16816(acc[mt][nt], af[mt], bf[nt]);
        }
    };

    // ---- proven 2-stage pipeline: 16 stages of K=32 ----
    load_stage(0, 0);
    asm volatile("cp.async.commit_group;");
    for (int ks = 0; ks < 16; ++ks) {
        if (ks + 1 < 16) {
            load_stage(ks + 1, (ks + 1) & 1);
            asm volatile("cp.async.commit_group;");
            asm volatile("cp.async.wait_group 1;");
        } else {
            asm volatile("cp.async.wait_group 0;");
        }
        __syncthreads();
        compute_stage(ks & 1);
        __syncthreads();
    }

    // epilogue: * invnorm[c], clip, * scale
#pragma unroll
    for (int mt = 0; mt < 4; ++mt) {
#pragma unroll
        for (int nt = 0; nt < 8; ++nt) {
            int col = colBase + wn * 64 + nt * 8 + (lane & 3) * 2;
            if (col >= C_DIM) continue;
            float2 inv = *reinterpret_cast<const float2*>(g_invnorm + col);
#pragma unroll
            for (int rr = 0; rr < 2; ++rr) {
                int row = rowBase + wm * 64 + mt * 16 + (lane >> 2) + rr * 8;
                float2 v;
                v.x = fminf(fmaxf(acc[mt][nt][rr * 2 + 0] * inv.x, -1.0f + EPS_F), 1.0f - EPS_F) * SCALE_F;
                v.y = fminf(fmaxf(acc[mt][nt][rr * 2 + 1] * inv.y, -1.0f + EPS_F), 1.0f - EPS_F) * SCALE_F;
                *reinterpret_cast<float2*>(out + (size_t)row * C_DIM + col) = v;
            }
        }
    }
}

// ---------------------------------------------------------------------------
// Kernel 5: patch label entries IN-PLACE from the GEMM output.
// ---------------------------------------------------------------------------
__global__ void patch_label_kernel(const float* __restrict__ norms,
                                   const int*   __restrict__ label,
                                   float* __restrict__ out)
{
    int b = blockIdx.x * blockDim.x + threadIdx.x;
    if (b >= B_DIM) return;

    int col = label[b];
    size_t idx = (size_t)b * C_DIM + col;
    float cosv = out[idx] * (1.0f / SCALE_F);   // already clipped

    float sn = fminf(fmaxf(norms[b], 1e-3f), 100.0f);
    float ms = sn / (100.0f + EPS_F) * 0.333f;        // BATCH_MEAN = 0
    ms = fminf(fmaxf(ms, -1.0f), 1.0f);

    float theta = acosf(cosv) + 0.5f * ms;            // M = 0.5
    const float PI_F = 3.14159265358979323846f;
    theta = fminf(fmaxf(theta, EPS_F), PI_F - EPS_F);
    float cm = cosf(theta) - (0.5f - 0.5f * ms);      // HEAD_B = 0.5
    out[idx] = cm * SCALE_F;
}

// ---------------------------------------------------------------------------
extern "C" void kernel_launch(void* const* d_in, const int* in_sizes, int n_in,
                              void* d_out, int out_size)
{
    const float* emb   = (const float*)d_in[0];  // [1024, 512]
    const float* norms = (const float*)d_in[1];  // [1024, 1]
    const float* kern  = (const float*)d_in[2];  // [512, 51332]
    const int*   label = (const int*)  d_in[3];  // [1024]
    float*       out   = (float*)d_out;          // [1024, 51332]

    dim3 pgrid(C_PAD / 128, 4);
    kprep_part_kernel<<<pgrid, 128>>>(kern);
    invnorm_kernel<<<(C_DIM + 255) / 256, 256>>>();

    ef16_kernel<<<(B_DIM * D_DIM / 4 + 255) / 256, 256>>>(emb);

    dim3 ggrid(B_DIM / 128, C_TILES);   // row tile fastest -> B slab L2 reuse
    gemm_f16_kernel<<<ggrid, 128>>>(out);

    patch_label_kernel<<<(B_DIM + 255) / 256, 256>>>(norms, label, out);
}